// round 8
// baseline (speedup 1.0000x reference)
#include <cuda_runtime.h>
#include <cuda_bf16.h>
#include <mma.h>
#include <math.h>
#include <stdint.h>

using namespace nvcuda;

#define E_ 8
#define H_ 1024
#define F_ 3584
#define T_ 4096

// ---------------------------------------------------------------------------
__device__ int   g_cnt[E_];
__device__ int   g_tok[E_ * T_];
__device__ float g_tokw[E_ * T_];
__device__ int   g_sel[T_ * 2];
__device__ float g_selw[T_ * 2];

__device__ __align__(128) __nv_bfloat16 g_xh[T_ * H_];
__device__ __align__(128) __nv_bfloat16 g_xl[T_ * H_];
__device__ __align__(128) __nv_bfloat16 g_wuT_h[E_ * F_ * H_];   // [E][F][H]
__device__ __align__(128) __nv_bfloat16 g_wuT_l[E_ * F_ * H_];
__device__ __align__(128) __nv_bfloat16 g_wgT_h[E_ * F_ * H_];
__device__ __align__(128) __nv_bfloat16 g_wgT_l[E_ * F_ * H_];
__device__ __align__(128) __nv_bfloat16 g_wdT_h[E_ * H_ * F_];   // [E][H][F]
__device__ __align__(128) __nv_bfloat16 g_wdT_l[E_ * H_ * F_];
__device__ __align__(128) __nv_bfloat16 g_in_h[(size_t)E_ * T_ * F_];
__device__ __align__(128) __nv_bfloat16 g_in_l[(size_t)E_ * T_ * F_];

// ---------------------------------------------------------------------------
__device__ __forceinline__ void cpa16(uint32_t dst, const void* src, bool v) {
    asm volatile("cp.async.cg.shared.global [%0], [%1], 16, %2;"
        :: "r"(dst), "l"(src), "r"(v ? 16u : 0u));
}
#define CP_COMMIT() asm volatile("cp.async.commit_group;" ::: "memory")
#define CP_WAIT(n)  asm volatile("cp.async.wait_group %0;" :: "n"(n) : "memory")

__device__ __forceinline__ uint32_t smem_u32(const void* p) {
    uint32_t a;
    asm("{ .reg .u64 t; cvta.to.shared.u64 t, %1; cvt.u32.u64 %0, t; }"
        : "=r"(a) : "l"(p));
    return a;
}

// ---------------------------------------------------------------------------
__global__ void zero_kernel(float* __restrict__ y) {
    int idx = blockIdx.x * blockDim.x + threadIdx.x;
    if (idx < T_ * H_) y[idx] = 0.0f;
    if (idx < E_) g_cnt[idx] = 0;
}

// ---------------------------------------------------------------------------
__global__ __launch_bounds__(256) void router_kernel(
    const float* __restrict__ x, const float* __restrict__ gw,
    float* __restrict__ logits_out) {
    __shared__ float s_gw[H_ * E_];
    int tid = threadIdx.x;
    for (int i = tid; i < H_ * E_; i += 256) s_gw[i] = gw[i];
    __syncthreads();

    int warp = tid >> 5, lane = tid & 31;
    int t = blockIdx.x * 8 + warp;

    float acc[E_];
#pragma unroll
    for (int e = 0; e < E_; e++) acc[e] = 0.0f;
    const float* xr = x + (size_t)t * H_;
    for (int h = lane; h < H_; h += 32) {
        float xv = xr[h];
#pragma unroll
        for (int e = 0; e < E_; e++) acc[e] += xv * s_gw[h * E_ + e];
    }
#pragma unroll
    for (int e = 0; e < E_; e++) {
#pragma unroll
        for (int off = 16; off > 0; off >>= 1)
            acc[e] += __shfl_xor_sync(0xffffffffu, acc[e], off);
    }
    if (lane == 0) {
        float m = acc[0];
#pragma unroll
        for (int e = 1; e < E_; e++) m = fmaxf(m, acc[e]);
        int e1 = 0; float v1 = acc[0];
#pragma unroll
        for (int e = 1; e < E_; e++) if (acc[e] > v1) { v1 = acc[e]; e1 = e; }
        int e2 = -1; float v2 = -INFINITY;
#pragma unroll
        for (int e = 0; e < E_; e++)
            if (e != e1 && acc[e] > v2) { v2 = acc[e]; e2 = e; }
        float p1 = expf(v1 - m), p2 = expf(v2 - m);
        float inv = 1.0f / (p1 + p2);
        g_sel[t * 2] = e1;  g_sel[t * 2 + 1] = e2;
        g_selw[t * 2] = p1 * inv;  g_selw[t * 2 + 1] = p2 * inv;
#pragma unroll
        for (int e = 0; e < E_; e++) logits_out[t * E_ + e] = acc[e];
    }
}

__global__ void compact_kernel() {
    int t = blockIdx.x * blockDim.x + threadIdx.x;
    if (t >= T_) return;
#pragma unroll
    for (int r = 0; r < 2; r++) {
        int e = g_sel[t * 2 + r];
        int pos = atomicAdd(&g_cnt[e], 1);
        g_tok[e * T_ + pos]  = t;
        g_tokw[e * T_ + pos] = g_selw[t * 2 + r];
    }
}

// ---------------------------------------------------------------------------
__global__ void convx_kernel(const float* __restrict__ x) {
    int idx = blockIdx.x * blockDim.x + threadIdx.x;
    if (idx >= T_ * H_) return;
    float v = x[idx];
    __nv_bfloat16 h = __float2bfloat16(v);
    g_xh[idx] = h;
    g_xl[idx] = __float2bfloat16(v - __bfloat162float(h));
}

// Transpose + split: in [E][R][C] fp32 -> out [E][C][R] bf16 hi/lo
__global__ __launch_bounds__(256) void convT_kernel(
    const float* __restrict__ in, __nv_bfloat16* __restrict__ oh,
    __nv_bfloat16* __restrict__ ol, int R, int C) {
    __shared__ float tile[32][33];
    int e = blockIdx.z;
    const float* src = in + (size_t)e * R * C;
    size_t obase = (size_t)e * R * C;
    int r0 = blockIdx.x * 32, c0 = blockIdx.y * 32;
    int tx = threadIdx.x & 31, ty = threadIdx.x >> 5;
#pragma unroll
    for (int j = 0; j < 4; j++) {
        int r = ty + j * 8;
        tile[r][tx] = src[(size_t)(r0 + r) * C + c0 + tx];
    }
    __syncthreads();
#pragma unroll
    for (int j = 0; j < 4; j++) {
        int c = ty + j * 8;
        float v = tile[tx][c];
        __nv_bfloat16 h = __float2bfloat16(v);
        size_t o = obase + (size_t)(c0 + c) * R + r0 + tx;
        oh[o] = h;
        ol[o] = __float2bfloat16(v - __bfloat162float(h));
    }
}

// ---------------------------------------------------------------------------
// GEMM1: CTA 128x128, 512 threads, 16 warps (4x4), warp tile 32x32, k-chunk 32
// smem/buffer: Ah/Al [128][40] + 4 B-planes [128][40] = 61440 B; x2 = 122880
// ---------------------------------------------------------------------------
#define G1_BUF 61440
#define G1_SMEM (2 * G1_BUF)

__global__ __launch_bounds__(512) void gemm1_tc() {
    extern __shared__ char smc[];
    __shared__ int s_tok[128];
    uint32_t sb = smem_u32(smc);

    int e = blockIdx.z;
    int M = g_cnt[e];
    int m0 = blockIdx.y * 128;
    if (m0 >= M) return;
    int n0 = blockIdx.x * 128;
    int tid = threadIdx.x, wid = tid >> 5, lid = tid & 31;

    if (tid < 128) {
        int gm = m0 + tid;
        s_tok[tid] = (gm < M) ? g_tok[e * T_ + gm] : -1;
    }
    __syncthreads();

    const __nv_bfloat16* bp[4];
    bp[0] = g_wuT_h + ((size_t)e * F_ + n0) * H_;
    bp[1] = g_wuT_l + ((size_t)e * F_ + n0) * H_;
    bp[2] = g_wgT_h + ((size_t)e * F_ + n0) * H_;
    bp[3] = g_wgT_l + ((size_t)e * F_ + n0) * H_;

    auto fill = [&](int b, int it) {
        int k0 = it * 32;
        uint32_t base = sb + b * G1_BUF;
        // A: 2 planes x 128 rows x 4 chunks = 1024 ops
#pragma unroll
        for (int j = 0; j < 2; j++) {
            int i = tid + j * 512;
            int p = i >> 9, rem = i & 511, row = rem >> 2, ch = rem & 3;
            int tok = s_tok[row];
            const char* src = (const char*)(p ? g_xl : g_xh)
                + ((((size_t)(tok < 0 ? 0 : tok)) * H_ + k0) << 1) + ch * 16;
            cpa16(base + p * 10240 + row * 80 + ch * 16, src, tok >= 0);
        }
        // B: 4 planes x 128 rows x 4 chunks = 2048 ops
#pragma unroll
        for (int j = 0; j < 4; j++) {
            int i = tid + j * 512;
            int p = i >> 9, rem = i & 511, row = rem >> 2, ch = rem & 3;
            const char* src = (const char*)bp[p]
                + (((size_t)row * H_ + k0) << 1) + ch * 16;
            cpa16(base + 20480 + p * 10240 + row * 80 + ch * 16, src, true);
        }
        CP_COMMIT();
    };

    wmma::fragment<wmma::accumulator, 16, 16, 16, float> U[2][2], G[2][2];
#pragma unroll
    for (int i = 0; i < 2; i++)
#pragma unroll
        for (int j = 0; j < 2; j++) {
            wmma::fill_fragment(U[i][j], 0.0f);
            wmma::fill_fragment(G[i][j], 0.0f);
        }

    int wm = wid >> 2, wn = wid & 3;   // 4x4 warp grid
    const int NIT = H_ / 32;
    fill(0, 0);

    for (int it = 0; it < NIT; it++) {
        int b = it & 1;
        if (it + 1 < NIT) fill(b ^ 1, it + 1);
        if (it + 1 < NIT) { CP_WAIT(1); } else { CP_WAIT(0); }
        __syncthreads();

        const __nv_bfloat16* Ah = (const __nv_bfloat16*)(smc + b * G1_BUF);
        const __nv_bfloat16* Al = (const __nv_bfloat16*)(smc + b * G1_BUF + 10240);
        const __nv_bfloat16* Bb = (const __nv_bfloat16*)(smc + b * G1_BUF + 20480);

#pragma unroll
        for (int ks = 0; ks < 2; ks++) {
            wmma::fragment<wmma::matrix_a, 16, 16, 16, __nv_bfloat16, wmma::row_major> ah[2], al[2];
#pragma unroll
            for (int i = 0; i < 2; i++) {
                wmma::load_matrix_sync(ah[i], Ah + (wm * 32 + i * 16) * 40 + ks * 16, 40);
                wmma::load_matrix_sync(al[i], Al + (wm * 32 + i * 16) * 40 + ks * 16, 40);
            }
            wmma::fragment<wmma::matrix_b, 16, 16, 16, __nv_bfloat16, wmma::col_major> bf[2];
            // U (up): hi then lo plane
#pragma unroll
            for (int j = 0; j < 2; j++)
                wmma::load_matrix_sync(bf[j], Bb + 0 * 5120 + (wn * 32 + j * 16) * 40 + ks * 16, 40);
#pragma unroll
            for (int i = 0; i < 2; i++)
#pragma unroll
                for (int j = 0; j < 2; j++) {
                    wmma::mma_sync(U[i][j], ah[i], bf[j], U[i][j]);
                    wmma::mma_sync(U[i][j], al[i], bf[j], U[i][j]);
                }
#pragma unroll
            for (int j = 0; j < 2; j++)
                wmma::load_matrix_sync(bf[j], Bb + 1 * 5120 + (wn * 32 + j * 16) * 40 + ks * 16, 40);
#pragma unroll
            for (int i = 0; i < 2; i++)
#pragma unroll
                for (int j = 0; j < 2; j++)
                    wmma::mma_sync(U[i][j], ah[i], bf[j], U[i][j]);
            // G (gate)
#pragma unroll
            for (int j = 0; j < 2; j++)
                wmma::load_matrix_sync(bf[j], Bb + 2 * 5120 + (wn * 32 + j * 16) * 40 + ks * 16, 40);
#pragma unroll
            for (int i = 0; i < 2; i++)
#pragma unroll
                for (int j = 0; j < 2; j++) {
                    wmma::mma_sync(G[i][j], ah[i], bf[j], G[i][j]);
                    wmma::mma_sync(G[i][j], al[i], bf[j], G[i][j]);
                }
#pragma unroll
            for (int j = 0; j < 2; j++)
                wmma::load_matrix_sync(bf[j], Bb + 3 * 5120 + (wn * 32 + j * 16) * 40 + ks * 16, 40);
#pragma unroll
            for (int i = 0; i < 2; i++)
#pragma unroll
                for (int j = 0; j < 2; j++)
                    wmma::mma_sync(G[i][j], ah[i], bf[j], G[i][j]);
        }
        __syncthreads();
    }

    // Fragment-level SwiGLU: U <- silu(U) * G (identical lane mappings)
#pragma unroll
    for (int i = 0; i < 2; i++)
#pragma unroll
        for (int j = 0; j < 2; j++)
#pragma unroll
            for (int t = 0; t < U[i][j].num_elements; t++) {
                float u = U[i][j].x[t];
                U[i][j].x[t] = (u / (1.0f + __expf(-u))) * G[i][j].x[t];
            }

    __syncthreads();   // all reads of final buffer done before staging overwrites

    // Stage single result fragment set (16 warps x 4608 B = 73728 <= 122880)
    float* stV = (float*)(smc + wid * 4608);
#pragma unroll
    for (int i = 0; i < 2; i++)
#pragma unroll
        for (int j = 0; j < 2; j++)
            wmma::store_matrix_sync(stV + i * 16 * 36 + j * 16, U[i][j], 36, wmma::mem_row_major);
    __syncwarp();

    int gm = m0 + wm * 32 + lid;
    if (gm < M) {
        size_t ob = ((size_t)e * T_ + gm) * F_ + n0 + wn * 32;
        uint32_t hb[16], lb[16];
#pragma unroll
        for (int c = 0; c < 16; c++) {
            float v0 = stV[lid * 36 + 2 * c];
            float v1 = stV[lid * 36 + 2 * c + 1];
            __nv_bfloat16 h0 = __float2bfloat16(v0);
            __nv_bfloat16 h1 = __float2bfloat16(v1);
            __nv_bfloat16 e0 = __float2bfloat16(v0 - __bfloat162float(h0));
            __nv_bfloat16 e1 = __float2bfloat16(v1 - __bfloat162float(h1));
            hb[c] = (uint32_t)__bfloat16_as_ushort(h0) | ((uint32_t)__bfloat16_as_ushort(h1) << 16);
            lb[c] = (uint32_t)__bfloat16_as_ushort(e0) | ((uint32_t)__bfloat16_as_ushort(e1) << 16);
        }
        uint4* dh = (uint4*)(g_in_h + ob);
        uint4* dl = (uint4*)(g_in_l + ob);
#pragma unroll
        for (int q = 0; q < 4; q++) {
            dh[q] = make_uint4(hb[4 * q], hb[4 * q + 1], hb[4 * q + 2], hb[4 * q + 3]);
            dl[q] = make_uint4(lb[4 * q], lb[4 * q + 1], lb[4 * q + 2], lb[4 * q + 3]);
        }
    }
}

// ---------------------------------------------------------------------------
// GEMM2: CTA 128x128, 512 threads, 16 warps (4x4), k over F
// smem/buffer: Ah/Al [128][40] + Bh/Bl [128][40] = 40960 B; x2 = 81920
// ---------------------------------------------------------------------------
#define G2_BUF 40960
#define G2_SMEM (2 * G2_BUF)

__global__ __launch_bounds__(512) void gemm2_tc(float* __restrict__ y) {
    extern __shared__ char smc[];
    uint32_t sb = smem_u32(smc);

    int e = blockIdx.z;
    int M = g_cnt[e];
    int m0 = blockIdx.y * 128;
    if (m0 >= M) return;
    int n0 = blockIdx.x * 128;
    int tid = threadIdx.x, wid = tid >> 5, lid = tid & 31;

    const __nv_bfloat16* bh = g_wdT_h + ((size_t)e * H_ + n0) * F_;
    const __nv_bfloat16* bl = g_wdT_l + ((size_t)e * H_ + n0) * F_;
    size_t abase = (size_t)e * T_ + m0;

    auto fill = [&](int b, int it) {
        int k0 = it * 32;
        uint32_t base = sb + b * G2_BUF;
#pragma unroll
        for (int j = 0; j < 2; j++) {
            int i = tid + j * 512;
            int p = i >> 9, rem = i & 511, row = rem >> 2, ch = rem & 3;
            bool valid = (m0 + row) < M;
            size_t srow = abase + (valid ? row : 0);
            const char* src = (const char*)(p ? g_in_l : g_in_h)
                + ((srow * F_ + k0) << 1) + ch * 16;
            cpa16(base + p * 10240 + row * 80 + ch * 16, src, valid);
        }
#pragma unroll
        for (int j = 0; j < 2; j++) {
            int i = tid + j * 512;
            int p = i >> 9, rem = i & 511, row = rem >> 2, ch = rem & 3;
            const char* src = (const char*)(p ? bl : bh)
                + (((size_t)row * F_ + k0) << 1) + ch * 16;
            cpa16(base + 20480 + p * 10240 + row * 80 + ch * 16, src, true);
        }
        CP_COMMIT();
    };

    wmma::fragment<wmma::accumulator, 16, 16, 16, float> D[2][2];
#pragma unroll
    for (int i = 0; i < 2; i++)
#pragma unroll
        for (int j = 0; j < 2; j++)
            wmma::fill_fragment(D[i][j], 0.0f);

    int wm = wid >> 2, wn = wid & 3;
    const int NIT = F_ / 32;
    fill(0, 0);

    for (int it = 0; it < NIT; it++) {
        int b = it & 1;
        if (it + 1 < NIT) fill(b ^ 1, it + 1);
        if (it + 1 < NIT) { CP_WAIT(1); } else { CP_WAIT(0); }
        __syncthreads();

        const __nv_bfloat16* Ah = (const __nv_bfloat16*)(smc + b * G2_BUF);
        const __nv_bfloat16* Al = (const __nv_bfloat16*)(smc + b * G2_BUF + 10240);
        const __nv_bfloat16* Bh = (const __nv_bfloat16*)(smc + b * G2_BUF + 20480);
        const __nv_bfloat16* Bl = (const __nv_bfloat16*)(smc + b * G2_BUF + 30720);

#pragma unroll
        for (int ks = 0; ks < 2; ks++) {
            wmma::fragment<wmma::matrix_a, 16, 16, 16, __nv_bfloat16, wmma::row_major> ah[2], al[2];
#pragma unroll
            for (int i = 0; i < 2; i++) {
                wmma::load_matrix_sync(ah[i], Ah + (wm * 32 + i * 16) * 40 + ks * 16, 40);
                wmma::load_matrix_sync(al[i], Al + (wm * 32 + i * 16) * 40 + ks * 16, 40);
            }
            wmma::fragment<wmma::matrix_b, 16, 16, 16, __nv_bfloat16, wmma::col_major> bf[2];
#pragma unroll
            for (int j = 0; j < 2; j++)
                wmma::load_matrix_sync(bf[j], Bh + (wn * 32 + j * 16) * 40 + ks * 16, 40);
#pragma unroll
            for (int i = 0; i < 2; i++)
#pragma unroll
                for (int j = 0; j < 2; j++) {
                    wmma::mma_sync(D[i][j], ah[i], bf[j], D[i][j]);
                    wmma::mma_sync(D[i][j], al[i], bf[j], D[i][j]);
                }
#pragma unroll
            for (int j = 0; j < 2; j++)
                wmma::load_matrix_sync(bf[j], Bl + (wn * 32 + j * 16) * 40 + ks * 16, 40);
#pragma unroll
            for (int i = 0; i < 2; i++)
#pragma unroll
                for (int j = 0; j < 2; j++)
                    wmma::mma_sync(D[i][j], ah[i], bf[j], D[i][j]);
        }
        __syncthreads();
    }

    // Epilogue: stage (16 x 4608 = 73728 <= 81920), scale, atomicAdd
    float* stD = (float*)(smc + wid * 4608);
#pragma unroll
    for (int i = 0; i < 2; i++)
#pragma unroll
        for (int j = 0; j < 2; j++)
            wmma::store_matrix_sync(stD + i * 16 * 36 + j * 16, D[i][j], 36, wmma::mem_row_major);
    __syncwarp();

    int gm = m0 + wm * 32 + lid;
    if (gm < M) {
        int   t  = g_tok[e * T_ + gm];
        float cw = g_tokw[e * T_ + gm];
        float* yr = y + (size_t)t * H_ + n0 + wn * 32;
#pragma unroll
        for (int c = 0; c < 32; c++)
            atomicAdd(&yr[c], cw * stD[lid * 36 + c]);
    }
}

// ---------------------------------------------------------------------------
extern "C" void kernel_launch(void* const* d_in, const int* in_sizes, int n_in,
                              void* d_out, int out_size) {
    const float* x      = (const float*)d_in[0];
    const float* gw     = (const float*)d_in[1];
    const float* w_up   = (const float*)d_in[2];
    const float* w_gate = (const float*)d_in[3];
    const float* w_down = (const float*)d_in[4];

    float* out    = (float*)d_out;
    float* y      = out;
    float* logits = out + (size_t)T_ * H_;

    cudaFuncSetAttribute(gemm1_tc, cudaFuncAttributeMaxDynamicSharedMemorySize, G1_SMEM);
    cudaFuncSetAttribute(gemm2_tc, cudaFuncAttributeMaxDynamicSharedMemorySize, G2_SMEM);

    zero_kernel<<<(T_ * H_ + 255) / 256, 256>>>(y);
    convx_kernel<<<(T_ * H_ + 255) / 256, 256>>>(x);

    __nv_bfloat16 *wuh, *wul, *wgh, *wgl, *wdh, *wdl;
    cudaGetSymbolAddress((void**)&wuh, g_wuT_h);
    cudaGetSymbolAddress((void**)&wul, g_wuT_l);
    cudaGetSymbolAddress((void**)&wgh, g_wgT_h);
    cudaGetSymbolAddress((void**)&wgl, g_wgT_l);
    cudaGetSymbolAddress((void**)&wdh, g_wdT_h);
    cudaGetSymbolAddress((void**)&wdl, g_wdT_l);

    convT_kernel<<<dim3(H_ / 32, F_ / 32, E_), 256>>>(w_up,   wuh, wul, H_, F_);
    convT_kernel<<<dim3(H_ / 32, F_ / 32, E_), 256>>>(w_gate, wgh, wgl, H_, F_);
    convT_kernel<<<dim3(F_ / 32, H_ / 32, E_), 256>>>(w_down, wdh, wdl, F_, H_);

    router_kernel<<<T_ / 8, 256>>>(x, gw, logits);
    compact_kernel<<<(T_ + 255) / 256, 256>>>();

    gemm1_tc<<<dim3(F_ / 128, T_ / 128, E_), 512, G1_SMEM>>>();
    gemm2_tc<<<dim3(H_ / 128, T_ / 128, E_), 512, G2_SMEM>>>(y);
}

// round 11
// speedup vs baseline: 1.7169x; 1.7169x over previous
#include <cuda_runtime.h>
#include <cuda_fp16.h>
#include <mma.h>
#include <math.h>
#include <stdint.h>

using namespace nvcuda;

#define E_ 8
#define H_ 1024
#define F_ 3584
#define T_ 4096

// ---------------------------------------------------------------------------
__device__ int   g_cnt[E_];
__device__ int   g_tok[E_ * T_];
__device__ float g_tokw[E_ * T_];
__device__ int   g_sel[T_ * 2];
__device__ float g_selw[T_ * 2];

__device__ __align__(128) __half g_xh[T_ * H_];
__device__ __align__(128) __half g_xl[T_ * H_];
__device__ __align__(128) __half g_wuT[E_ * F_ * H_];   // [E][F][H] fp16
__device__ __align__(128) __half g_wgT[E_ * F_ * H_];
__device__ __align__(128) __half g_wdT[E_ * H_ * F_];   // [E][H][F] fp16
__device__ __align__(128) __half g_in_h[(size_t)E_ * T_ * F_];
__device__ __align__(128) __half g_in_l[(size_t)E_ * T_ * F_];

// ---------------------------------------------------------------------------
__device__ __forceinline__ void cpa16(uint32_t dst, const void* src, bool v) {
    asm volatile("cp.async.cg.shared.global [%0], [%1], 16, %2;"
        :: "r"(dst), "l"(src), "r"(v ? 16u : 0u));
}
#define CP_COMMIT() asm volatile("cp.async.commit_group;" ::: "memory")
#define CP_WAIT(n)  asm volatile("cp.async.wait_group %0;" :: "n"(n) : "memory")

__device__ __forceinline__ uint32_t smem_u32(const void* p) {
    uint32_t a;
    asm("{ .reg .u64 t; cvta.to.shared.u64 t, %1; cvt.u32.u64 %0, t; }"
        : "=r"(a) : "l"(p));
    return a;
}

// ---------------------------------------------------------------------------
__global__ void zero_kernel(float* __restrict__ y) {
    int idx = blockIdx.x * blockDim.x + threadIdx.x;
    if (idx < T_ * H_) y[idx] = 0.0f;
    if (idx < E_) g_cnt[idx] = 0;
}

// ---------------------------------------------------------------------------
__global__ __launch_bounds__(256) void router_kernel(
    const float* __restrict__ x, const float* __restrict__ gw,
    float* __restrict__ logits_out) {
    __shared__ float s_gw[H_ * E_];
    int tid = threadIdx.x;
    for (int i = tid; i < H_ * E_; i += 256) s_gw[i] = gw[i];
    __syncthreads();

    int warp = tid >> 5, lane = tid & 31;
    int t = blockIdx.x * 8 + warp;

    float acc[E_];
#pragma unroll
    for (int e = 0; e < E_; e++) acc[e] = 0.0f;
    const float* xr = x + (size_t)t * H_;
    for (int h = lane; h < H_; h += 32) {
        float xv = xr[h];
#pragma unroll
        for (int e = 0; e < E_; e++) acc[e] += xv * s_gw[h * E_ + e];
    }
#pragma unroll
    for (int e = 0; e < E_; e++) {
#pragma unroll
        for (int off = 16; off > 0; off >>= 1)
            acc[e] += __shfl_xor_sync(0xffffffffu, acc[e], off);
    }
    if (lane == 0) {
        float m = acc[0];
#pragma unroll
        for (int e = 1; e < E_; e++) m = fmaxf(m, acc[e]);
        int e1 = 0; float v1 = acc[0];
#pragma unroll
        for (int e = 1; e < E_; e++) if (acc[e] > v1) { v1 = acc[e]; e1 = e; }
        int e2 = -1; float v2 = -INFINITY;
#pragma unroll
        for (int e = 0; e < E_; e++)
            if (e != e1 && acc[e] > v2) { v2 = acc[e]; e2 = e; }
        float p1 = expf(v1 - m), p2 = expf(v2 - m);
        float inv = 1.0f / (p1 + p2);
        g_sel[t * 2] = e1;  g_sel[t * 2 + 1] = e2;
        g_selw[t * 2] = p1 * inv;  g_selw[t * 2 + 1] = p2 * inv;
#pragma unroll
        for (int e = 0; e < E_; e++) logits_out[t * E_ + e] = acc[e];
    }
}

__global__ void compact_kernel() {
    int t = blockIdx.x * blockDim.x + threadIdx.x;
    if (t >= T_) return;
#pragma unroll
    for (int r = 0; r < 2; r++) {
        int e = g_sel[t * 2 + r];
        int pos = atomicAdd(&g_cnt[e], 1);
        g_tok[e * T_ + pos]  = t;
        g_tokw[e * T_ + pos] = g_selw[t * 2 + r];
    }
}

// ---------------------------------------------------------------------------
// x -> fp16 hi/lo planes
__global__ void convx_kernel(const float* __restrict__ x) {
    int idx = blockIdx.x * blockDim.x + threadIdx.x;
    if (idx >= T_ * H_) return;
    float v = x[idx];
    __half h = __float2half(v);
    g_xh[idx] = h;
    g_xl[idx] = __float2half(v - __half2float(h));
}

// Transpose: in [E][R][C] fp32 -> out [E][C][R] fp16 (single plane)
__global__ __launch_bounds__(256) void convT_kernel(
    const float* __restrict__ in, __half* __restrict__ o, int R, int C) {
    __shared__ float tile[32][33];
    int e = blockIdx.z;
    const float* src = in + (size_t)e * R * C;
    size_t obase = (size_t)e * R * C;
    int r0 = blockIdx.x * 32, c0 = blockIdx.y * 32;
    int tx = threadIdx.x & 31, ty = threadIdx.x >> 5;
#pragma unroll
    for (int j = 0; j < 4; j++) {
        int r = ty + j * 8;
        tile[r][tx] = src[(size_t)(r0 + r) * C + c0 + tx];
    }
    __syncthreads();
#pragma unroll
    for (int j = 0; j < 4; j++) {
        int c = ty + j * 8;
        o[obase + (size_t)(c0 + c) * R + r0 + tx] = __float2half(tile[tx][c]);
    }
}

// ---------------------------------------------------------------------------
// GEMM1: CTA 128x64, 256 threads, 8 warps (4x2), warp tile 32x32, k-chunk 32
// smem/buffer: Ah/Al [128][40] + Bu/Bg [64][40] = 30720 B; x2 = 61440
// D = Ah*B + Al*B  (fp16 2-term)
// ---------------------------------------------------------------------------
#define G1_BUF 30720
#define G1_SMEM (2 * G1_BUF)

__global__ __launch_bounds__(256) void gemm1_tc() {
    extern __shared__ char smc[];
    __shared__ int s_tok[128];
    uint32_t sb = smem_u32(smc);

    int e = blockIdx.z;
    int M = g_cnt[e];
    int m0 = blockIdx.y * 128;
    if (m0 >= M) return;
    int n0 = blockIdx.x * 64;
    int tid = threadIdx.x, wid = tid >> 5, lid = tid & 31;

    if (tid < 128) {
        int gm = m0 + tid;
        s_tok[tid] = (gm < M) ? g_tok[e * T_ + gm] : -1;
    }
    __syncthreads();

    const __half* bu = g_wuT + ((size_t)e * F_ + n0) * H_;
    const __half* bg = g_wgT + ((size_t)e * F_ + n0) * H_;

    auto fill = [&](int b, int it) {
        int k0 = it * 32;
        uint32_t base = sb + b * G1_BUF;
        // A: 2 planes x 128 rows x 4 chunks = 1024 ops
#pragma unroll
        for (int j = 0; j < 4; j++) {
            int i = tid + j * 256;
            int p = i >> 9, rem = i & 511, row = rem >> 2, ch = rem & 3;
            int tok = s_tok[row];
            const char* src = (const char*)(p ? g_xl : g_xh)
                + ((((size_t)(tok < 0 ? 0 : tok)) * H_ + k0) << 1) + ch * 16;
            cpa16(base + p * 10240 + row * 80 + ch * 16, src, tok >= 0);
        }
        // B: 2 mats x 64 rows x 4 chunks = 512 ops
#pragma unroll
        for (int j = 0; j < 2; j++) {
            int i = tid + j * 256;
            int p = i >> 8, rem = i & 255, row = rem >> 2, ch = rem & 3;
            const char* src = (const char*)(p ? bg : bu)
                + (((size_t)row * H_ + k0) << 1) + ch * 16;
            cpa16(base + 20480 + p * 5120 + row * 80 + ch * 16, src, true);
        }
        CP_COMMIT();
    };

    wmma::fragment<wmma::accumulator, 16, 16, 16, float> U[2][2], G[2][2];
#pragma unroll
    for (int i = 0; i < 2; i++)
#pragma unroll
        for (int j = 0; j < 2; j++) {
            wmma::fill_fragment(U[i][j], 0.0f);
            wmma::fill_fragment(G[i][j], 0.0f);
        }

    int wm = wid >> 1, wn = wid & 1;
    const int NIT = H_ / 32;
    fill(0, 0);

    for (int it = 0; it < NIT; it++) {
        int b = it & 1;
        if (it + 1 < NIT) fill(b ^ 1, it + 1);
        if (it + 1 < NIT) { CP_WAIT(1); } else { CP_WAIT(0); }
        __syncthreads();

        const __half* Ah = (const __half*)(smc + b * G1_BUF);
        const __half* Al = (const __half*)(smc + b * G1_BUF + 10240);
        const __half* Bu = (const __half*)(smc + b * G1_BUF + 20480);
        const __half* Bg = (const __half*)(smc + b * G1_BUF + 25600);

#pragma unroll
        for (int ks = 0; ks < 2; ks++) {
            wmma::fragment<wmma::matrix_a, 16, 16, 16, __half, wmma::row_major> ah[2], al[2];
#pragma unroll
            for (int i = 0; i < 2; i++) {
                wmma::load_matrix_sync(ah[i], Ah + (wm * 32 + i * 16) * 40 + ks * 16, 40);
                wmma::load_matrix_sync(al[i], Al + (wm * 32 + i * 16) * 40 + ks * 16, 40);
            }
            wmma::fragment<wmma::matrix_b, 16, 16, 16, __half, wmma::col_major> bf[2];
#pragma unroll
            for (int j = 0; j < 2; j++)
                wmma::load_matrix_sync(bf[j], Bu + (wn * 32 + j * 16) * 40 + ks * 16, 40);
#pragma unroll
            for (int i = 0; i < 2; i++)
#pragma unroll
                for (int j = 0; j < 2; j++) {
                    wmma::mma_sync(U[i][j], ah[i], bf[j], U[i][j]);
                    wmma::mma_sync(U[i][j], al[i], bf[j], U[i][j]);
                }
#pragma unroll
            for (int j = 0; j < 2; j++)
                wmma::load_matrix_sync(bf[j], Bg + (wn * 32 + j * 16) * 40 + ks * 16, 40);
#pragma unroll
            for (int i = 0; i < 2; i++)
#pragma unroll
                for (int j = 0; j < 2; j++) {
                    wmma::mma_sync(G[i][j], ah[i], bf[j], G[i][j]);
                    wmma::mma_sync(G[i][j], al[i], bf[j], G[i][j]);
                }
        }
        __syncthreads();
    }

    // Fragment-level SwiGLU: U <- silu(U) * G (identical lane mappings)
#pragma unroll
    for (int i = 0; i < 2; i++)
#pragma unroll
        for (int j = 0; j < 2; j++)
#pragma unroll
            for (int t = 0; t < U[i][j].num_elements; t++) {
                float u = U[i][j].x[t];
                U[i][j].x[t] = (u / (1.0f + __expf(-u))) * G[i][j].x[t];
            }

    // Stage result (8 warps x 4608 B = 36864 <= 61440)
    float* stV = (float*)(smc + wid * 4608);
#pragma unroll
    for (int i = 0; i < 2; i++)
#pragma unroll
        for (int j = 0; j < 2; j++)
            wmma::store_matrix_sync(stV + i * 16 * 36 + j * 16, U[i][j], 36, wmma::mem_row_major);
    __syncwarp();

    int gm = m0 + wm * 32 + lid;
    if (gm < M) {
        size_t ob = ((size_t)e * T_ + gm) * F_ + n0 + wn * 32;
        uint32_t hb[16], lb[16];
#pragma unroll
        for (int c = 0; c < 16; c++) {
            float v0 = stV[lid * 36 + 2 * c];
            float v1 = stV[lid * 36 + 2 * c + 1];
            __half h0 = __float2half(v0);
            __half h1 = __float2half(v1);
            __half e0 = __float2half(v0 - __half2float(h0));
            __half e1 = __float2half(v1 - __half2float(h1));
            hb[c] = (uint32_t)__half_as_ushort(h0) | ((uint32_t)__half_as_ushort(h1) << 16);
            lb[c] = (uint32_t)__half_as_ushort(e0) | ((uint32_t)__half_as_ushort(e1) << 16);
        }
        uint4* dh = (uint4*)(g_in_h + ob);
        uint4* dl = (uint4*)(g_in_l + ob);
#pragma unroll
        for (int q = 0; q < 4; q++) {
            dh[q] = make_uint4(hb[4 * q], hb[4 * q + 1], hb[4 * q + 2], hb[4 * q + 3]);
            dl[q] = make_uint4(lb[4 * q], lb[4 * q + 1], lb[4 * q + 2], lb[4 * q + 3]);
        }
    }
}

// ---------------------------------------------------------------------------
// GEMM2: CTA 128x64, 256 threads, k over F, D = Ah*B + Al*B (fp16 2-term)
// smem/buffer: Ah/Al [128][40] + B [64][40] = 25600 B; x2 = 51200
// ---------------------------------------------------------------------------
#define G2_BUF 25600
#define G2_SMEM (2 * G2_BUF)

__global__ __launch_bounds__(256) void gemm2_tc(float* __restrict__ y) {
    extern __shared__ char smc[];
    uint32_t sb = smem_u32(smc);

    int e = blockIdx.z;
    int M = g_cnt[e];
    int m0 = blockIdx.y * 128;
    if (m0 >= M) return;
    int n0 = blockIdx.x * 64;
    int tid = threadIdx.x, wid = tid >> 5, lid = tid & 31;

    const __half* bd = g_wdT + ((size_t)e * H_ + n0) * F_;
    size_t abase = (size_t)e * T_ + m0;

    auto fill = [&](int b, int it) {
        int k0 = it * 32;
        uint32_t base = sb + b * G2_BUF;
        // A: 2 planes x 128 rows x 4 chunks = 1024 ops
#pragma unroll
        for (int j = 0; j < 4; j++) {
            int i = tid + j * 256;
            int p = i >> 9, rem = i & 511, row = rem >> 2, ch = rem & 3;
            bool valid = (m0 + row) < M;
            size_t srow = abase + (valid ? row : 0);
            const char* src = (const char*)(p ? g_in_l : g_in_h)
                + ((srow * F_ + k0) << 1) + ch * 16;
            cpa16(base + p * 10240 + row * 80 + ch * 16, src, valid);
        }
        // B: 1 plane x 64 rows x 4 chunks = 256 ops
        {
            int i = tid;
            int row = i >> 2, ch = i & 3;
            const char* src = (const char*)bd
                + (((size_t)row * F_ + k0) << 1) + ch * 16;
            cpa16(base + 20480 + row * 80 + ch * 16, src, true);
        }
        CP_COMMIT();
    };

    wmma::fragment<wmma::accumulator, 16, 16, 16, float> D[2][2];
#pragma unroll
    for (int i = 0; i < 2; i++)
#pragma unroll
        for (int j = 0; j < 2; j++)
            wmma::fill_fragment(D[i][j], 0.0f);

    int wm = wid >> 1, wn = wid & 1;
    const int NIT = F_ / 32;
    fill(0, 0);

    for (int it = 0; it < NIT; it++) {
        int b = it & 1;
        if (it + 1 < NIT) fill(b ^ 1, it + 1);
        if (it + 1 < NIT) { CP_WAIT(1); } else { CP_WAIT(0); }
        __syncthreads();

        const __half* Ah = (const __half*)(smc + b * G2_BUF);
        const __half* Al = (const __half*)(smc + b * G2_BUF + 10240);
        const __half* Bd = (const __half*)(smc + b * G2_BUF + 20480);

#pragma unroll
        for (int ks = 0; ks < 2; ks++) {
            wmma::fragment<wmma::matrix_a, 16, 16, 16, __half, wmma::row_major> ah[2], al[2];
#pragma unroll
            for (int i = 0; i < 2; i++) {
                wmma::load_matrix_sync(ah[i], Ah + (wm * 32 + i * 16) * 40 + ks * 16, 40);
                wmma::load_matrix_sync(al[i], Al + (wm * 32 + i * 16) * 40 + ks * 16, 40);
            }
            wmma::fragment<wmma::matrix_b, 16, 16, 16, __half, wmma::col_major> bf[2];
#pragma unroll
            for (int j = 0; j < 2; j++)
                wmma::load_matrix_sync(bf[j], Bd + (wn * 32 + j * 16) * 40 + ks * 16, 40);
#pragma unroll
            for (int i = 0; i < 2; i++)
#pragma unroll
                for (int j = 0; j < 2; j++) {
                    wmma::mma_sync(D[i][j], ah[i], bf[j], D[i][j]);
                    wmma::mma_sync(D[i][j], al[i], bf[j], D[i][j]);
                }
        }
        __syncthreads();
    }

    // Epilogue: stage (8 x 4608 = 36864 <= 51200), scale, atomicAdd
    float* stD = (float*)(smc + wid * 4608);
#pragma unroll
    for (int i = 0; i < 2; i++)
#pragma unroll
        for (int j = 0; j < 2; j++)
            wmma::store_matrix_sync(stD + i * 16 * 36 + j * 16, D[i][j], 36, wmma::mem_row_major);
    __syncwarp();

    int gm = m0 + wm * 32 + lid;
    if (gm < M) {
        int   t  = g_tok[e * T_ + gm];
        float cw = g_tokw[e * T_ + gm];
        float* yr = y + (size_t)t * H_ + n0 + wn * 32;
#pragma unroll
        for (int c = 0; c < 32; c++)
            atomicAdd(&yr[c], cw * stD[lid * 36 + c]);
    }
}

// ---------------------------------------------------------------------------
extern "C" void kernel_launch(void* const* d_in, const int* in_sizes, int n_in,
                              void* d_out, int out_size) {
    const float* x      = (const float*)d_in[0];
    const float* gw     = (const float*)d_in[1];
    const float* w_up   = (const float*)d_in[2];
    const float* w_gate = (const float*)d_in[3];
    const float* w_down = (const float*)d_in[4];

    float* out    = (float*)d_out;
    float* y      = out;
    float* logits = out + (size_t)T_ * H_;

    cudaFuncSetAttribute(gemm1_tc, cudaFuncAttributeMaxDynamicSharedMemorySize, G1_SMEM);
    cudaFuncSetAttribute(gemm2_tc, cudaFuncAttributeMaxDynamicSharedMemorySize, G2_SMEM);

    zero_kernel<<<(T_ * H_ + 255) / 256, 256>>>(y);
    convx_kernel<<<(T_ * H_ + 255) / 256, 256>>>(x);

    __half *wu, *wg, *wd;
    cudaGetSymbolAddress((void**)&wu, g_wuT);
    cudaGetSymbolAddress((void**)&wg, g_wgT);
    cudaGetSymbolAddress((void**)&wd, g_wdT);

    convT_kernel<<<dim3(H_ / 32, F_ / 32, E_), 256>>>(w_up,   wu, H_, F_);
    convT_kernel<<<dim3(H_ / 32, F_ / 32, E_), 256>>>(w_gate, wg, H_, F_);
    convT_kernel<<<dim3(F_ / 32, H_ / 32, E_), 256>>>(w_down, wd, F_, H_);

    router_kernel<<<T_ / 8, 256>>>(x, gw, logits);
    compact_kernel<<<(T_ + 255) / 256, 256>>>();

    gemm1_tc<<<dim3(F_ / 64, T_ / 128, E_), 256, G1_SMEM>>>();
    gemm2_tc<<<dim3(H_ / 64, T_ / 128, E_), 256, G2_SMEM>>>(y);
}

// round 16
// speedup vs baseline: 1.9341x; 1.1265x over previous
#include <cuda_runtime.h>
#include <cuda_fp16.h>
#include <mma.h>
#include <math.h>
#include <stdint.h>

using namespace nvcuda;

#define E_ 8
#define H_ 1024
#define F_ 3584
#define T_ 4096

// ---------------------------------------------------------------------------
__device__ int   g_cnt[E_];
__device__ int   g_tok[E_ * T_];
__device__ float g_tokw[E_ * T_];
__device__ int   g_sel[T_ * 2];
__device__ float g_selw[T_ * 2];

__device__ __align__(128) __half g_xh[T_ * H_];
__device__ __align__(128) __half g_xl[T_ * H_];
__device__ __align__(128) __half g_wuT[E_ * F_ * H_];   // [E][F][H] fp16
__device__ __align__(128) __half g_wgT[E_ * F_ * H_];
__device__ __align__(128) __half g_wdT[E_ * H_ * F_];   // [E][H][F] fp16
__device__ __align__(128) __half g_in_h[(size_t)E_ * T_ * F_];  // single fp16 plane

// ---------------------------------------------------------------------------
__device__ __forceinline__ void cpa16(uint32_t dst, const void* src, bool v) {
    asm volatile("cp.async.cg.shared.global [%0], [%1], 16, %2;"
        :: "r"(dst), "l"(src), "r"(v ? 16u : 0u));
}
#define CP_COMMIT() asm volatile("cp.async.commit_group;" ::: "memory")
#define CP_WAIT(n)  asm volatile("cp.async.wait_group %0;" :: "n"(n) : "memory")

__device__ __forceinline__ uint32_t smem_u32(const void* p) {
    uint32_t a;
    asm("{ .reg .u64 t; cvta.to.shared.u64 t, %1; cvt.u32.u64 %0, t; }"
        : "=r"(a) : "l"(p));
    return a;
}

// ---------------------------------------------------------------------------
__global__ void zero_kernel(float* __restrict__ y) {
    int idx = blockIdx.x * blockDim.x + threadIdx.x;
    if (idx < T_ * H_) y[idx] = 0.0f;
    if (idx < E_) g_cnt[idx] = 0;
}

// ---------------------------------------------------------------------------
__global__ __launch_bounds__(256) void router_kernel(
    const float* __restrict__ x, const float* __restrict__ gw,
    float* __restrict__ logits_out) {
    __shared__ float s_gw[H_ * E_];
    int tid = threadIdx.x;
    for (int i = tid; i < H_ * E_; i += 256) s_gw[i] = gw[i];
    __syncthreads();

    int warp = tid >> 5, lane = tid & 31;
    int t = blockIdx.x * 8 + warp;

    float acc[E_];
#pragma unroll
    for (int e = 0; e < E_; e++) acc[e] = 0.0f;
    const float* xr = x + (size_t)t * H_;
    for (int h = lane; h < H_; h += 32) {
        float xv = xr[h];
#pragma unroll
        for (int e = 0; e < E_; e++) acc[e] += xv * s_gw[h * E_ + e];
    }
#pragma unroll
    for (int e = 0; e < E_; e++) {
#pragma unroll
        for (int off = 16; off > 0; off >>= 1)
            acc[e] += __shfl_xor_sync(0xffffffffu, acc[e], off);
    }
    if (lane == 0) {
        float m = acc[0];
#pragma unroll
        for (int e = 1; e < E_; e++) m = fmaxf(m, acc[e]);
        int e1 = 0; float v1 = acc[0];
#pragma unroll
        for (int e = 1; e < E_; e++) if (acc[e] > v1) { v1 = acc[e]; e1 = e; }
        int e2 = -1; float v2 = -INFINITY;
#pragma unroll
        for (int e = 0; e < E_; e++)
            if (e != e1 && acc[e] > v2) { v2 = acc[e]; e2 = e; }
        float p1 = expf(v1 - m), p2 = expf(v2 - m);
        float inv = 1.0f / (p1 + p2);
        g_sel[t * 2] = e1;  g_sel[t * 2 + 1] = e2;
        g_selw[t * 2] = p1 * inv;  g_selw[t * 2 + 1] = p2 * inv;
#pragma unroll
        for (int e = 0; e < E_; e++) logits_out[t * E_ + e] = acc[e];
    }
}

__global__ void compact_kernel() {
    int t = blockIdx.x * blockDim.x + threadIdx.x;
    if (t >= T_) return;
#pragma unroll
    for (int r = 0; r < 2; r++) {
        int e = g_sel[t * 2 + r];
        int pos = atomicAdd(&g_cnt[e], 1);
        g_tok[e * T_ + pos]  = t;
        g_tokw[e * T_ + pos] = g_selw[t * 2 + r];
    }
}

// ---------------------------------------------------------------------------
// x -> fp16 hi/lo planes
__global__ void convx_kernel(const float* __restrict__ x) {
    int idx = blockIdx.x * blockDim.x + threadIdx.x;
    if (idx >= T_ * H_) return;
    float v = x[idx];
    __half h = __float2half(v);
    g_xh[idx] = h;
    g_xl[idx] = __float2half(v - __half2float(h));
}

// Transpose: in [E][R][C] fp32 -> out [E][C][R] fp16 (single plane)
__global__ __launch_bounds__(256) void convT_kernel(
    const float* __restrict__ in, __half* __restrict__ o, int R, int C) {
    __shared__ float tile[32][33];
    int e = blockIdx.z;
    const float* src = in + (size_t)e * R * C;
    size_t obase = (size_t)e * R * C;
    int r0 = blockIdx.x * 32, c0 = blockIdx.y * 32;
    int tx = threadIdx.x & 31, ty = threadIdx.x >> 5;
#pragma unroll
    for (int j = 0; j < 4; j++) {
        int r = ty + j * 8;
        tile[r][tx] = src[(size_t)(r0 + r) * C + c0 + tx];
    }
    __syncthreads();
#pragma unroll
    for (int j = 0; j < 4; j++) {
        int c = ty + j * 8;
        o[obase + (size_t)(c0 + c) * R + r0 + tx] = __float2half(tile[tx][c]);
    }
}

// ---------------------------------------------------------------------------
// GEMM1: CTA 128x64, 256 threads, 8 warps (4x2), warp tile 32x32, k-chunk 32
// smem/buffer: Ah/Al [128][40] + Bu/Bg [64][40] = 30720 B; x2 = 61440
// D = Ah*B + Al*B  (fp16 2-term)
// ---------------------------------------------------------------------------
#define G1_BUF 30720
#define G1_SMEM (2 * G1_BUF)

__global__ __launch_bounds__(256) void gemm1_tc() {
    extern __shared__ char smc[];
    __shared__ int s_tok[128];
    uint32_t sb = smem_u32(smc);

    int e = blockIdx.z;
    int M = g_cnt[e];
    int m0 = blockIdx.y * 128;
    if (m0 >= M) return;
    int n0 = blockIdx.x * 64;
    int tid = threadIdx.x, wid = tid >> 5, lid = tid & 31;

    if (tid < 128) {
        int gm = m0 + tid;
        s_tok[tid] = (gm < M) ? g_tok[e * T_ + gm] : -1;
    }
    __syncthreads();

    const __half* bu = g_wuT + ((size_t)e * F_ + n0) * H_;
    const __half* bg = g_wgT + ((size_t)e * F_ + n0) * H_;

    auto fill = [&](int b, int it) {
        int k0 = it * 32;
        uint32_t base = sb + b * G1_BUF;
        // A: 2 planes x 128 rows x 4 chunks = 1024 ops
#pragma unroll
        for (int j = 0; j < 4; j++) {
            int i = tid + j * 256;
            int p = i >> 9, rem = i & 511, row = rem >> 2, ch = rem & 3;
            int tok = s_tok[row];
            const char* src = (const char*)(p ? g_xl : g_xh)
                + ((((size_t)(tok < 0 ? 0 : tok)) * H_ + k0) << 1) + ch * 16;
            cpa16(base + p * 10240 + row * 80 + ch * 16, src, tok >= 0);
        }
        // B: 2 mats x 64 rows x 4 chunks = 512 ops
#pragma unroll
        for (int j = 0; j < 2; j++) {
            int i = tid + j * 256;
            int p = i >> 8, rem = i & 255, row = rem >> 2, ch = rem & 3;
            const char* src = (const char*)(p ? bg : bu)
                + (((size_t)row * H_ + k0) << 1) + ch * 16;
            cpa16(base + 20480 + p * 5120 + row * 80 + ch * 16, src, true);
        }
        CP_COMMIT();
    };

    wmma::fragment<wmma::accumulator, 16, 16, 16, float> U[2][2], G[2][2];
#pragma unroll
    for (int i = 0; i < 2; i++)
#pragma unroll
        for (int j = 0; j < 2; j++) {
            wmma::fill_fragment(U[i][j], 0.0f);
            wmma::fill_fragment(G[i][j], 0.0f);
        }

    int wm = wid >> 1, wn = wid & 1;
    const int NIT = H_ / 32;
    fill(0, 0);

    for (int it = 0; it < NIT; it++) {
        int b = it & 1;
        if (it + 1 < NIT) fill(b ^ 1, it + 1);
        if (it + 1 < NIT) { CP_WAIT(1); } else { CP_WAIT(0); }
        __syncthreads();

        const __half* Ah = (const __half*)(smc + b * G1_BUF);
        const __half* Al = (const __half*)(smc + b * G1_BUF + 10240);
        const __half* Bu = (const __half*)(smc + b * G1_BUF + 20480);
        const __half* Bg = (const __half*)(smc + b * G1_BUF + 25600);

#pragma unroll
        for (int ks = 0; ks < 2; ks++) {
            wmma::fragment<wmma::matrix_a, 16, 16, 16, __half, wmma::row_major> ah[2], al[2];
#pragma unroll
            for (int i = 0; i < 2; i++) {
                wmma::load_matrix_sync(ah[i], Ah + (wm * 32 + i * 16) * 40 + ks * 16, 40);
                wmma::load_matrix_sync(al[i], Al + (wm * 32 + i * 16) * 40 + ks * 16, 40);
            }
            wmma::fragment<wmma::matrix_b, 16, 16, 16, __half, wmma::col_major> bf[2];
#pragma unroll
            for (int j = 0; j < 2; j++)
                wmma::load_matrix_sync(bf[j], Bu + (wn * 32 + j * 16) * 40 + ks * 16, 40);
#pragma unroll
            for (int i = 0; i < 2; i++)
#pragma unroll
                for (int j = 0; j < 2; j++) {
                    wmma::mma_sync(U[i][j], ah[i], bf[j], U[i][j]);
                    wmma::mma_sync(U[i][j], al[i], bf[j], U[i][j]);
                }
#pragma unroll
            for (int j = 0; j < 2; j++)
                wmma::load_matrix_sync(bf[j], Bg + (wn * 32 + j * 16) * 40 + ks * 16, 40);
#pragma unroll
            for (int i = 0; i < 2; i++)
#pragma unroll
                for (int j = 0; j < 2; j++) {
                    wmma::mma_sync(G[i][j], ah[i], bf[j], G[i][j]);
                    wmma::mma_sync(G[i][j], al[i], bf[j], G[i][j]);
                }
        }
        __syncthreads();
    }

    // Fragment-level SwiGLU: U <- silu(U) * G (identical lane mappings)
#pragma unroll
    for (int i = 0; i < 2; i++)
#pragma unroll
        for (int j = 0; j < 2; j++)
#pragma unroll
            for (int t = 0; t < U[i][j].num_elements; t++) {
                float u = U[i][j].x[t];
                U[i][j].x[t] = (u / (1.0f + __expf(-u))) * G[i][j].x[t];
            }

    // Stage result (8 warps x 4608 B = 36864 <= 61440)
    float* stV = (float*)(smc + wid * 4608);
#pragma unroll
    for (int i = 0; i < 2; i++)
#pragma unroll
        for (int j = 0; j < 2; j++)
            wmma::store_matrix_sync(stV + i * 16 * 36 + j * 16, U[i][j], 36, wmma::mem_row_major);
    __syncwarp();

    int gm = m0 + wm * 32 + lid;
    if (gm < M) {
        size_t ob = ((size_t)e * T_ + gm) * F_ + n0 + wn * 32;
        uint32_t hb[16];
#pragma unroll
        for (int c = 0; c < 16; c++) {
            float v0 = stV[lid * 36 + 2 * c];
            float v1 = stV[lid * 36 + 2 * c + 1];
            __half h0 = __float2half(v0);
            __half h1 = __float2half(v1);
            hb[c] = (uint32_t)__half_as_ushort(h0) | ((uint32_t)__half_as_ushort(h1) << 16);
        }
        uint4* dh = (uint4*)(g_in_h + ob);
#pragma unroll
        for (int q = 0; q < 4; q++)
            dh[q] = make_uint4(hb[4 * q], hb[4 * q + 1], hb[4 * q + 2], hb[4 * q + 3]);
    }
}

// ---------------------------------------------------------------------------
// GEMM2: CTA 128x64, 256 threads, k over F, D = A*B (fp16 single-term)
// smem/buffer: A [128][40] + B [64][40] = 15360 B; x2 = 30720 (alloc 36864 for staging)
// ---------------------------------------------------------------------------
#define G2_BUF 15360
#define G2_SMEM 36864

__global__ __launch_bounds__(256) void gemm2_tc(float* __restrict__ y) {
    extern __shared__ char smc[];
    uint32_t sb = smem_u32(smc);

    int e = blockIdx.z;
    int M = g_cnt[e];
    int m0 = blockIdx.y * 128;
    if (m0 >= M) return;
    int n0 = blockIdx.x * 64;
    int tid = threadIdx.x, wid = tid >> 5, lid = tid & 31;

    const __half* bd = g_wdT + ((size_t)e * H_ + n0) * F_;
    size_t abase = (size_t)e * T_ + m0;

    auto fill = [&](int b, int it) {
        int k0 = it * 32;
        uint32_t base = sb + b * G2_BUF;
        // A: 1 plane x 128 rows x 4 chunks = 512 ops
#pragma unroll
        for (int j = 0; j < 2; j++) {
            int i = tid + j * 256;
            int row = i >> 2, ch = i & 3;
            bool valid = (m0 + row) < M;
            size_t srow = abase + (valid ? row : 0);
            const char* src = (const char*)g_in_h
                + ((srow * F_ + k0) << 1) + ch * 16;
            cpa16(base + row * 80 + ch * 16, src, valid);
        }
        // B: 1 plane x 64 rows x 4 chunks = 256 ops
        {
            int i = tid;
            int row = i >> 2, ch = i & 3;
            const char* src = (const char*)bd
                + (((size_t)row * F_ + k0) << 1) + ch * 16;
            cpa16(base + 10240 + row * 80 + ch * 16, src, true);
        }
        CP_COMMIT();
    };

    wmma::fragment<wmma::accumulator, 16, 16, 16, float> D[2][2];
#pragma unroll
    for (int i = 0; i < 2; i++)
#pragma unroll
        for (int j = 0; j < 2; j++)
            wmma::fill_fragment(D[i][j], 0.0f);

    int wm = wid >> 1, wn = wid & 1;
    const int NIT = F_ / 32;
    fill(0, 0);

    for (int it = 0; it < NIT; it++) {
        int b = it & 1;
        if (it + 1 < NIT) fill(b ^ 1, it + 1);
        if (it + 1 < NIT) { CP_WAIT(1); } else { CP_WAIT(0); }
        __syncthreads();

        const __half* A  = (const __half*)(smc + b * G2_BUF);
        const __half* Bd = (const __half*)(smc + b * G2_BUF + 10240);

#pragma unroll
        for (int ks = 0; ks < 2; ks++) {
            wmma::fragment<wmma::matrix_a, 16, 16, 16, __half, wmma::row_major> af[2];
#pragma unroll
            for (int i = 0; i < 2; i++)
                wmma::load_matrix_sync(af[i], A + (wm * 32 + i * 16) * 40 + ks * 16, 40);
            wmma::fragment<wmma::matrix_b, 16, 16, 16, __half, wmma::col_major> bf[2];
#pragma unroll
            for (int j = 0; j < 2; j++)
                wmma::load_matrix_sync(bf[j], Bd + (wn * 32 + j * 16) * 40 + ks * 16, 40);
#pragma unroll
            for (int i = 0; i < 2; i++)
#pragma unroll
                for (int j = 0; j < 2; j++)
                    wmma::mma_sync(D[i][j], af[i], bf[j], D[i][j]);
        }
        __syncthreads();
    }

    // Epilogue: stage (8 x 4608 = 36864 <= G2_SMEM), scale, atomicAdd
    float* stD = (float*)(smc + wid * 4608);
#pragma unroll
    for (int i = 0; i < 2; i++)
#pragma unroll
        for (int j = 0; j < 2; j++)
            wmma::store_matrix_sync(stD + i * 16 * 36 + j * 16, D[i][j], 36, wmma::mem_row_major);
    __syncwarp();

    int gm = m0 + wm * 32 + lid;
    if (gm < M) {
        int   t  = g_tok[e * T_ + gm];
        float cw = g_tokw[e * T_ + gm];
        float* yr = y + (size_t)t * H_ + n0 + wn * 32;
#pragma unroll
        for (int c = 0; c < 32; c++)
            atomicAdd(&yr[c], cw * stD[lid * 36 + c]);
    }
}

// ---------------------------------------------------------------------------
extern "C" void kernel_launch(void* const* d_in, const int* in_sizes, int n_in,
                              void* d_out, int out_size) {
    const float* x      = (const float*)d_in[0];
    const float* gw     = (const float*)d_in[1];
    const float* w_up   = (const float*)d_in[2];
    const float* w_gate = (const float*)d_in[3];
    const float* w_down = (const float*)d_in[4];

    float* out    = (float*)d_out;
    float* y      = out;
    float* logits = out + (size_t)T_ * H_;

    cudaFuncSetAttribute(gemm1_tc, cudaFuncAttributeMaxDynamicSharedMemorySize, G1_SMEM);
    cudaFuncSetAttribute(gemm2_tc, cudaFuncAttributeMaxDynamicSharedMemorySize, G2_SMEM);

    zero_kernel<<<(T_ * H_ + 255) / 256, 256>>>(y);
    convx_kernel<<<(T_ * H_ + 255) / 256, 256>>>(x);

    __half *wu, *wg, *wd;
    cudaGetSymbolAddress((void**)&wu, g_wuT);
    cudaGetSymbolAddress((void**)&wg, g_wgT);
    cudaGetSymbolAddress((void**)&wd, g_wdT);

    convT_kernel<<<dim3(H_ / 32, F_ / 32, E_), 256>>>(w_up,   wu, H_, F_);
    convT_kernel<<<dim3(H_ / 32, F_ / 32, E_), 256>>>(w_gate, wg, H_, F_);
    convT_kernel<<<dim3(F_ / 32, H_ / 32, E_), 256>>>(w_down, wd, F_, H_);

    router_kernel<<<T_ / 8, 256>>>(x, gw, logits);
    compact_kernel<<<(T_ + 255) / 256, 256>>>();

    gemm1_tc<<<dim3(F_ / 64, T_ / 128, E_), 256, G1_SMEM>>>();
    gemm2_tc<<<dim3(H_ / 64, T_ / 128, E_), 256, G2_SMEM>>>(y);
}

// round 17
// speedup vs baseline: 2.5117x; 1.2987x over previous
#include <cuda_runtime.h>
#include <cuda_fp16.h>
#include <mma.h>
#include <math.h>
#include <stdint.h>

using namespace nvcuda;

#define E_ 8
#define H_ 1024
#define F_ 3584
#define T_ 4096

// ---------------------------------------------------------------------------
__device__ int   g_cnt[E_];
__device__ int   g_tok[E_ * T_];
__device__ float g_tokw[E_ * T_];
__device__ int   g_sel[T_ * 2];
__device__ float g_selw[T_ * 2];

__device__ __align__(128) __half g_xh[T_ * H_];
__device__ __align__(128) __half g_wuT[E_ * F_ * H_];   // [E][F][H] fp16
__device__ __align__(128) __half g_wgT[E_ * F_ * H_];
__device__ __align__(128) __half g_wdT[E_ * H_ * F_];   // [E][H][F] fp16
__device__ __align__(128) __half g_in_h[(size_t)E_ * T_ * F_];  // single fp16 plane

// ---------------------------------------------------------------------------
__device__ __forceinline__ void cpa16(uint32_t dst, const void* src, bool v) {
    asm volatile("cp.async.cg.shared.global [%0], [%1], 16, %2;"
        :: "r"(dst), "l"(src), "r"(v ? 16u : 0u));
}
#define CP_COMMIT() asm volatile("cp.async.commit_group;" ::: "memory")
#define CP_WAIT(n)  asm volatile("cp.async.wait_group %0;" :: "n"(n) : "memory")

__device__ __forceinline__ uint32_t smem_u32(const void* p) {
    uint32_t a;
    asm("{ .reg .u64 t; cvta.to.shared.u64 t, %1; cvt.u32.u64 %0, t; }"
        : "=r"(a) : "l"(p));
    return a;
}

// ---------------------------------------------------------------------------
__global__ void zero_kernel(float* __restrict__ y) {
    int idx = blockIdx.x * blockDim.x + threadIdx.x;
    if (idx < T_ * H_) y[idx] = 0.0f;
    if (idx < E_) g_cnt[idx] = 0;
}

// ---------------------------------------------------------------------------
__global__ __launch_bounds__(256) void router_kernel(
    const float* __restrict__ x, const float* __restrict__ gw,
    float* __restrict__ logits_out) {
    __shared__ float s_gw[H_ * E_];
    int tid = threadIdx.x;
    for (int i = tid; i < H_ * E_; i += 256) s_gw[i] = gw[i];
    __syncthreads();

    int warp = tid >> 5, lane = tid & 31;
    int t = blockIdx.x * 8 + warp;

    float acc[E_];
#pragma unroll
    for (int e = 0; e < E_; e++) acc[e] = 0.0f;
    const float* xr = x + (size_t)t * H_;
    for (int h = lane; h < H_; h += 32) {
        float xv = xr[h];
#pragma unroll
        for (int e = 0; e < E_; e++) acc[e] += xv * s_gw[h * E_ + e];
    }
#pragma unroll
    for (int e = 0; e < E_; e++) {
#pragma unroll
        for (int off = 16; off > 0; off >>= 1)
            acc[e] += __shfl_xor_sync(0xffffffffu, acc[e], off);
    }
    if (lane == 0) {
        float m = acc[0];
#pragma unroll
        for (int e = 1; e < E_; e++) m = fmaxf(m, acc[e]);
        int e1 = 0; float v1 = acc[0];
#pragma unroll
        for (int e = 1; e < E_; e++) if (acc[e] > v1) { v1 = acc[e]; e1 = e; }
        int e2 = -1; float v2 = -INFINITY;
#pragma unroll
        for (int e = 0; e < E_; e++)
            if (e != e1 && acc[e] > v2) { v2 = acc[e]; e2 = e; }
        float p1 = expf(v1 - m), p2 = expf(v2 - m);
        float inv = 1.0f / (p1 + p2);
        g_sel[t * 2] = e1;  g_sel[t * 2 + 1] = e2;
        g_selw[t * 2] = p1 * inv;  g_selw[t * 2 + 1] = p2 * inv;
#pragma unroll
        for (int e = 0; e < E_; e++) logits_out[t * E_ + e] = acc[e];
    }
}

__global__ void compact_kernel() {
    int t = blockIdx.x * blockDim.x + threadIdx.x;
    if (t >= T_) return;
#pragma unroll
    for (int r = 0; r < 2; r++) {
        int e = g_sel[t * 2 + r];
        int pos = atomicAdd(&g_cnt[e], 1);
        g_tok[e * T_ + pos]  = t;
        g_tokw[e * T_ + pos] = g_selw[t * 2 + r];
    }
}

// ---------------------------------------------------------------------------
// x -> fp16 (single plane)
__global__ void convx_kernel(const float* __restrict__ x) {
    int idx = blockIdx.x * blockDim.x + threadIdx.x;
    if (idx >= T_ * H_) return;
    g_xh[idx] = __float2half(x[idx]);
}

// Transpose: in [E][R][C] fp32 -> out [E][C][R] fp16 (single plane)
__global__ __launch_bounds__(256) void convT_kernel(
    const float* __restrict__ in, __half* __restrict__ o, int R, int C) {
    __shared__ float tile[32][33];
    int e = blockIdx.z;
    const float* src = in + (size_t)e * R * C;
    size_t obase = (size_t)e * R * C;
    int r0 = blockIdx.x * 32, c0 = blockIdx.y * 32;
    int tx = threadIdx.x & 31, ty = threadIdx.x >> 5;
#pragma unroll
    for (int j = 0; j < 4; j++) {
        int r = ty + j * 8;
        tile[r][tx] = src[(size_t)(r0 + r) * C + c0 + tx];
    }
    __syncthreads();
#pragma unroll
    for (int j = 0; j < 4; j++) {
        int c = ty + j * 8;
        o[obase + (size_t)(c0 + c) * R + r0 + tx] = __float2half(tile[tx][c]);
    }
}

// ---------------------------------------------------------------------------
// GEMM1: CTA 128x64, 256 threads, 8 warps (4x2), warp tile 32x32, k-chunk 32
// smem/buffer: A [128][40] + Bu/Bg [64][40] = 20480 B; x2 = 40960
// U = A*Bu, G = A*Bg (single-term fp16)
// ---------------------------------------------------------------------------
#define G1_BUF 20480
#define G1_SMEM (2 * G1_BUF)

__global__ __launch_bounds__(256) void gemm1_tc() {
    extern __shared__ char smc[];
    __shared__ int s_tok[128];
    uint32_t sb = smem_u32(smc);

    int e = blockIdx.z;
    int M = g_cnt[e];
    int m0 = blockIdx.y * 128;
    if (m0 >= M) return;
    int n0 = blockIdx.x * 64;
    int tid = threadIdx.x, wid = tid >> 5, lid = tid & 31;

    if (tid < 128) {
        int gm = m0 + tid;
        s_tok[tid] = (gm < M) ? g_tok[e * T_ + gm] : -1;
    }
    __syncthreads();

    const __half* bu = g_wuT + ((size_t)e * F_ + n0) * H_;
    const __half* bg = g_wgT + ((size_t)e * F_ + n0) * H_;

    auto fill = [&](int b, int it) {
        int k0 = it * 32;
        uint32_t base = sb + b * G1_BUF;
        // A: 128 rows x 4 chunks = 512 ops
#pragma unroll
        for (int j = 0; j < 2; j++) {
            int i = tid + j * 256;
            int row = i >> 2, ch = i & 3;
            int tok = s_tok[row];
            const char* src = (const char*)g_xh
                + ((((size_t)(tok < 0 ? 0 : tok)) * H_ + k0) << 1) + ch * 16;
            cpa16(base + row * 80 + ch * 16, src, tok >= 0);
        }
        // B: 2 mats x 64 rows x 4 chunks = 512 ops
#pragma unroll
        for (int j = 0; j < 2; j++) {
            int i = tid + j * 256;
            int p = i >> 8, rem = i & 255, row = rem >> 2, ch = rem & 3;
            const char* src = (const char*)(p ? bg : bu)
                + (((size_t)row * H_ + k0) << 1) + ch * 16;
            cpa16(base + 10240 + p * 5120 + row * 80 + ch * 16, src, true);
        }
        CP_COMMIT();
    };

    wmma::fragment<wmma::accumulator, 16, 16, 16, float> U[2][2], G[2][2];
#pragma unroll
    for (int i = 0; i < 2; i++)
#pragma unroll
        for (int j = 0; j < 2; j++) {
            wmma::fill_fragment(U[i][j], 0.0f);
            wmma::fill_fragment(G[i][j], 0.0f);
        }

    int wm = wid >> 1, wn = wid & 1;
    const int NIT = H_ / 32;
    fill(0, 0);

    for (int it = 0; it < NIT; it++) {
        int b = it & 1;
        if (it + 1 < NIT) fill(b ^ 1, it + 1);
        if (it + 1 < NIT) { CP_WAIT(1); } else { CP_WAIT(0); }
        __syncthreads();

        const __half* A  = (const __half*)(smc + b * G1_BUF);
        const __half* Bu = (const __half*)(smc + b * G1_BUF + 10240);
        const __half* Bg = (const __half*)(smc + b * G1_BUF + 15360);

#pragma unroll
        for (int ks = 0; ks < 2; ks++) {
            wmma::fragment<wmma::matrix_a, 16, 16, 16, __half, wmma::row_major> af[2];
#pragma unroll
            for (int i = 0; i < 2; i++)
                wmma::load_matrix_sync(af[i], A + (wm * 32 + i * 16) * 40 + ks * 16, 40);
            wmma::fragment<wmma::matrix_b, 16, 16, 16, __half, wmma::col_major> bf[2];
#pragma unroll
            for (int j = 0; j < 2; j++)
                wmma::load_matrix_sync(bf[j], Bu + (wn * 32 + j * 16) * 40 + ks * 16, 40);
#pragma unroll
            for (int i = 0; i < 2; i++)
#pragma unroll
                for (int j = 0; j < 2; j++)
                    wmma::mma_sync(U[i][j], af[i], bf[j], U[i][j]);
#pragma unroll
            for (int j = 0; j < 2; j++)
                wmma::load_matrix_sync(bf[j], Bg + (wn * 32 + j * 16) * 40 + ks * 16, 40);
#pragma unroll
            for (int i = 0; i < 2; i++)
#pragma unroll
                for (int j = 0; j < 2; j++)
                    wmma::mma_sync(G[i][j], af[i], bf[j], G[i][j]);
        }
        __syncthreads();
    }

    // Fragment-level SwiGLU: U <- silu(U) * G (identical lane mappings)
#pragma unroll
    for (int i = 0; i < 2; i++)
#pragma unroll
        for (int j = 0; j < 2; j++)
#pragma unroll
            for (int t = 0; t < U[i][j].num_elements; t++) {
                float u = U[i][j].x[t];
                U[i][j].x[t] = (u / (1.0f + __expf(-u))) * G[i][j].x[t];
            }

    // Stage result (8 warps x 4608 B = 36864 <= 40960)
    float* stV = (float*)(smc + wid * 4608);
#pragma unroll
    for (int i = 0; i < 2; i++)
#pragma unroll
        for (int j = 0; j < 2; j++)
            wmma::store_matrix_sync(stV + i * 16 * 36 + j * 16, U[i][j], 36, wmma::mem_row_major);
    __syncwarp();

    int gm = m0 + wm * 32 + lid;
    if (gm < M) {
        size_t ob = ((size_t)e * T_ + gm) * F_ + n0 + wn * 32;
        uint32_t hb[16];
#pragma unroll
        for (int c = 0; c < 16; c++) {
            float v0 = stV[lid * 36 + 2 * c];
            float v1 = stV[lid * 36 + 2 * c + 1];
            __half h0 = __float2half(v0);
            __half h1 = __float2half(v1);
            hb[c] = (uint32_t)__half_as_ushort(h0) | ((uint32_t)__half_as_ushort(h1) << 16);
        }
        uint4* dh = (uint4*)(g_in_h + ob);
#pragma unroll
        for (int q = 0; q < 4; q++)
            dh[q] = make_uint4(hb[4 * q], hb[4 * q + 1], hb[4 * q + 2], hb[4 * q + 3]);
    }
}

// ---------------------------------------------------------------------------
// GEMM2: CTA 128x64, 256 threads, k over F, D = A*B (fp16 single-term)
// smem/buffer: A [128][40] + B [64][40] = 15360 B; x2 = 30720 (alloc 36864 for staging)
// ---------------------------------------------------------------------------
#define G2_BUF 15360
#define G2_SMEM 36864

__global__ __launch_bounds__(256) void gemm2_tc(float* __restrict__ y) {
    extern __shared__ char smc[];
    uint32_t sb = smem_u32(smc);

    int e = blockIdx.z;
    int M = g_cnt[e];
    int m0 = blockIdx.y * 128;
    if (m0 >= M) return;
    int n0 = blockIdx.x * 64;
    int tid = threadIdx.x, wid = tid >> 5, lid = tid & 31;

    const __half* bd = g_wdT + ((size_t)e * H_ + n0) * F_;
    size_t abase = (size_t)e * T_ + m0;

    auto fill = [&](int b, int it) {
        int k0 = it * 32;
        uint32_t base = sb + b * G2_BUF;
        // A: 128 rows x 4 chunks = 512 ops
#pragma unroll
        for (int j = 0; j < 2; j++) {
            int i = tid + j * 256;
            int row = i >> 2, ch = i & 3;
            bool valid = (m0 + row) < M;
            size_t srow = abase + (valid ? row : 0);
            const char* src = (const char*)g_in_h
                + ((srow * F_ + k0) << 1) + ch * 16;
            cpa16(base + row * 80 + ch * 16, src, valid);
        }
        // B: 64 rows x 4 chunks = 256 ops
        {
            int i = tid;
            int row = i >> 2, ch = i & 3;
            const char* src = (const char*)bd
                + (((size_t)row * F_ + k0) << 1) + ch * 16;
            cpa16(base + 10240 + row * 80 + ch * 16, src, true);
        }
        CP_COMMIT();
    };

    wmma::fragment<wmma::accumulator, 16, 16, 16, float> D[2][2];
#pragma unroll
    for (int i = 0; i < 2; i++)
#pragma unroll
        for (int j = 0; j < 2; j++)
            wmma::fill_fragment(D[i][j], 0.0f);

    int wm = wid >> 1, wn = wid & 1;
    const int NIT = F_ / 32;
    fill(0, 0);

    for (int it = 0; it < NIT; it++) {
        int b = it & 1;
        if (it + 1 < NIT) fill(b ^ 1, it + 1);
        if (it + 1 < NIT) { CP_WAIT(1); } else { CP_WAIT(0); }
        __syncthreads();

        const __half* A  = (const __half*)(smc + b * G2_BUF);
        const __half* Bd = (const __half*)(smc + b * G2_BUF + 10240);

#pragma unroll
        for (int ks = 0; ks < 2; ks++) {
            wmma::fragment<wmma::matrix_a, 16, 16, 16, __half, wmma::row_major> af[2];
#pragma unroll
            for (int i = 0; i < 2; i++)
                wmma::load_matrix_sync(af[i], A + (wm * 32 + i * 16) * 40 + ks * 16, 40);
            wmma::fragment<wmma::matrix_b, 16, 16, 16, __half, wmma::col_major> bf[2];
#pragma unroll
            for (int j = 0; j < 2; j++)
                wmma::load_matrix_sync(bf[j], Bd + (wn * 32 + j * 16) * 40 + ks * 16, 40);
#pragma unroll
            for (int i = 0; i < 2; i++)
#pragma unroll
                for (int j = 0; j < 2; j++)
                    wmma::mma_sync(D[i][j], af[i], bf[j], D[i][j]);
        }
        __syncthreads();
    }

    // Epilogue: stage (8 x 4608 = 36864 <= G2_SMEM), scale, atomicAdd
    float* stD = (float*)(smc + wid * 4608);
#pragma unroll
    for (int i = 0; i < 2; i++)
#pragma unroll
        for (int j = 0; j < 2; j++)
            wmma::store_matrix_sync(stD + i * 16 * 36 + j * 16, D[i][j], 36, wmma::mem_row_major);
    __syncwarp();

    int gm = m0 + wm * 32 + lid;
    if (gm < M) {
        int   t  = g_tok[e * T_ + gm];
        float cw = g_tokw[e * T_ + gm];
        float* yr = y + (size_t)t * H_ + n0 + wn * 32;
#pragma unroll
        for (int c = 0; c < 32; c++)
            atomicAdd(&yr[c], cw * stD[lid * 36 + c]);
    }
}

// ---------------------------------------------------------------------------
extern "C" void kernel_launch(void* const* d_in, const int* in_sizes, int n_in,
                              void* d_out, int out_size) {
    const float* x      = (const float*)d_in[0];
    const float* gw     = (const float*)d_in[1];
    const float* w_up   = (const float*)d_in[2];
    const float* w_gate = (const float*)d_in[3];
    const float* w_down = (const float*)d_in[4];

    float* out    = (float*)d_out;
    float* y      = out;
    float* logits = out + (size_t)T_ * H_;

    cudaFuncSetAttribute(gemm1_tc, cudaFuncAttributeMaxDynamicSharedMemorySize, G1_SMEM);
    cudaFuncSetAttribute(gemm2_tc, cudaFuncAttributeMaxDynamicSharedMemorySize, G2_SMEM);

    zero_kernel<<<(T_ * H_ + 255) / 256, 256>>>(y);
    convx_kernel<<<(T_ * H_ + 255) / 256, 256>>>(x);

    __half *wu, *wg, *wd;
    cudaGetSymbolAddress((void**)&wu, g_wuT);
    cudaGetSymbolAddress((void**)&wg, g_wgT);
    cudaGetSymbolAddress((void**)&wd, g_wdT);

    convT_kernel<<<dim3(H_ / 32, F_ / 32, E_), 256>>>(w_up,   wu, H_, F_);
    convT_kernel<<<dim3(H_ / 32, F_ / 32, E_), 256>>>(w_gate, wg, H_, F_);
    convT_kernel<<<dim3(F_ / 32, H_ / 32, E_), 256>>>(w_down, wd, F_, H_);

    router_kernel<<<T_ / 8, 256>>>(x, gw, logits);
    compact_kernel<<<(T_ + 255) / 256, 256>>>();

    gemm1_tc<<<dim3(F_ / 64, T_ / 128, E_), 256, G1_SMEM>>>();
    gemm2_tc<<<dim3(H_ / 64, T_ / 128, E_), 256, G2_SMEM>>>(y);
}